// round 15
// baseline (speedup 1.0000x reference)
#include <cuda_runtime.h>
#include <math.h>

#define LUTN  1024
#define NGRID 140
#define NTHR  512

// ---------------- device scratch (zero-initialized at load) ----------------
__device__ float    d_binW[257], d_binWE[257];   // cycle 0 -> full -> 0 each launch
__device__ float    g_outAcc[64];                // atomic out partials, reset by block 0
__device__ float    g_Cp[8][128], g_Dp[8][128];
__device__ float    g_uvp[4][2][128];
__device__ float    g_rsp[8][2][256];
__device__ float    g_gsu[129], g_guA[129], g_guB[129], g_gst[257];
__device__ unsigned g_glut[LUTN];
__device__ float    g_gmaxv;
__device__ float    g_rr[256], g_ss[256];
__device__ int      g_pos[256];
__device__ unsigned g_epoch, g_cd, g_uv, g_tab, g_flush, g_tail;

// Proven idioms: ALL threads fence, then sync, then tid0 tickets.
__device__ __forceinline__ void sigall(unsigned* c) {
    __threadfence();
    __syncthreads();
    if (threadIdx.x == 0) atomicAdd(c, 1u);
}
__device__ __forceinline__ void waitge(unsigned* c, unsigned target) {
    if (threadIdx.x == 0) {
        for (;;) {
            unsigned cur;
            asm volatile("ld.volatile.global.u32 %0, [%1];" : "=r"(cur) : "l"(c) : "memory");
            if ((int)(cur - target) >= 0) break;
            __nanosleep(256);
        }
        __threadfence();
    }
    __syncthreads();
}

__global__ __launch_bounds__(NTHR, 1)
void kAll(const float* __restrict__ adj, int P,
          const float* __restrict__ W1a, const float* __restrict__ b1a,
          const float* __restrict__ W1b, const float* __restrict__ b1b,
          const float* __restrict__ W2a, const float* __restrict__ b2a,
          const float* __restrict__ W2b, const float* __restrict__ b2b,
          const float* __restrict__ W3a, const float* __restrict__ b3a,
          const float* __restrict__ W3b, const float* __restrict__ b3b,
          const float* __restrict__ W4a, const float* __restrict__ b4a,
          const float* __restrict__ W4b, const float* __restrict__ b4b,
          float* __restrict__ out)
{
    __shared__ float s_pa[4][128], s_pb[4][128];
    __shared__ float s_pr[2][256], s_ps[2][256];
    __shared__ float s_C[128], s_D[128];
    __shared__ float s_cu[128], s_cv[128], s_cw2b[128];
    __shared__ float s_ctk[256], s_cuk[128];
    __shared__ int   s_cuo[128];
    __shared__ unsigned short s_lutU[LUTN], s_lutV[LUTN];
    __shared__ float s_su[129], s_uA[129], s_uB[129];
    __shared__ float s_st[257];
    __shared__ unsigned s_lut[LUTN];
    __shared__ float s_bW[257], s_bWE[257];
    __shared__ float s_wa[16], s_wb[16];
    __shared__ float s_PF[257], s_PG[257];
    __shared__ float s_Hn[256], s_Wt[128], s_h4[64];
    __shared__ float s_red[NTHR];
    __shared__ unsigned s_ep;

    int tid = threadIdx.x, bid = blockIdx.x;
    int lane = tid & 31, wid = tid >> 5;
    int col = tid & 127, team = tid >> 7;      // 4 teams of 128

    if (tid == 0) s_ep = atomicAdd(&g_epoch, 1u) / NGRID;
    __syncthreads();
    unsigned ep = s_ep;

    // ---------- adj register preload: covers ALL edges (overlaps setup) ----------
    const float4* a4 = (const float4*)adj;
    int nq = P >> 2;
    int stride = NGRID * NTHR;
    int q0 = bid * NTHR + tid, q1 = q0 + stride;
    float4 e0 = make_float4(2.f,2.f,2.f,2.f), e1 = make_float4(2.f,2.f,2.f,2.f);
    if (q0 < nq) e0 = __ldg(a4 + q0);
    if (q1 < nq) e1 = __ldg(a4 + q1);

    // ================= phase A: C/D partials (blocks 0-7, 32 W1b rows each) =================
    if (bid < 8) {
        int colA = tid & 127, slot = tid >> 7;           // 4 slots x 8 rows
        float c = 0.f, d = 0.f;
        #pragma unroll
        for (int rr = 0; rr < 8; rr++) {
            int j = bid * 32 + slot * 8 + rr;
            float a = __ldg(W1a + j), b = __ldg(b1a + j);
            float w = __ldg(W1b + j * 128 + colA);
            if (fmaf(a, 0.5f, b) > 0.f) { c = fmaf(a, w, c); d = fmaf(b, w, d); }
        }
        s_pa[slot][colA] = c; s_pb[slot][colA] = d;
        __syncthreads();
        if (tid < 128) {
            g_Cp[bid][tid] = s_pa[0][tid] + s_pa[1][tid] + s_pa[2][tid] + s_pa[3][tid];
            g_Dp[bid][tid] = s_pb[0][tid] + s_pb[1][tid] + s_pb[2][tid] + s_pb[3][tid];
        }
        sigall(&g_cd);
    }

    // ================= phase B: u/v (blocks 0-3), r/s (blocks 4-11) partials =================
    if (bid < 12) {
        waitge(&g_cd, (ep + 1u) * 8u);
        if (tid < 128) {
            float c = 0.f, d = 0.f;
            #pragma unroll
            for (int b = 0; b < 8; b++) { c += g_Cp[b][tid]; d += g_Dp[b][tid]; }
            s_C[tid] = c; s_D[tid] = d + __ldg(b1b + tid);
        }
        __syncthreads();
        if (bid < 4) {
            int colA = tid & 127, slot = tid >> 7;       // 4 slots x 8 rows of W2a
            float uu = 0.f, vv = 0.f;
            #pragma unroll
            for (int rr = 0; rr < 8; rr++) {
                int k = bid * 32 + slot * 8 + rr;
                float w = __ldg(W2a + k * 128 + colA);
                uu = fmaf(s_C[k], w, uu); vv = fmaf(s_D[k], w, vv);
            }
            s_pa[slot][colA] = uu; s_pb[slot][colA] = vv;
            __syncthreads();
            if (tid < 128) {
                g_uvp[bid][0][tid] = s_pa[0][tid] + s_pa[1][tid] + s_pa[2][tid] + s_pa[3][tid];
                g_uvp[bid][1][tid] = s_pb[0][tid] + s_pb[1][tid] + s_pb[2][tid] + s_pb[3][tid];
            }
        } else {
            int kb = bid - 4;
            int colB = tid & 255, slot = tid >> 8;       // 2 slots x 16 rows of W3a
            float r = 0.f, sv = 0.f;
            #pragma unroll
            for (int rr = 0; rr < 16; rr++) {
                int k = kb * 32 + slot * 16 + rr;
                float w = __ldg(W3a + k * 256 + colB);
                r = fmaf(s_C[k], w, r); sv = fmaf(s_D[k], w, sv);
            }
            s_pr[slot][colB] = r; s_ps[slot][colB] = sv;
            __syncthreads();
            if (tid < 256) {
                g_rsp[kb][0][tid] = s_pr[0][tid] + s_pr[1][tid];
                g_rsp[kb][1][tid] = s_ps[0][tid] + s_ps[1][tid];
            }
        }
        sigall(&g_uv);
    }

    // ================= phase C: block 0 builds tables from partials =================
    if (bid == 0) {
        waitge(&g_uv, (ep + 1u) * 12u);
        if (tid < 128) {
            float u = 0.f, v = 0.f;
            #pragma unroll
            for (int b = 0; b < 4; b++) { u += g_uvp[b][0][tid]; v += g_uvp[b][1][tid]; }
            s_cu[tid] = u; s_cv[tid] = v + __ldg(b2a + tid);
            s_cw2b[tid] = __ldg(W2b + tid);
        }
        if (tid < 256) {
            float r = 0.f, sv = 0.f;
            #pragma unroll
            for (int b = 0; b < 8; b++) { r += g_rsp[b][0][tid]; sv += g_rsp[b][1][tid]; }
            sv += __ldg(b3a + tid);
            g_rr[tid] = r; g_ss[tid] = sv;               // publish (plain stores)
            float key = 1.0f;
            if (r != 0.f) key = fminf(fmaxf(-sv / r, 0.f), 1.f);
            s_ctk[tid] = key;
        }
        __syncthreads();
        if (tid < 128) {
            float uu = s_cu[tid], vv = s_cv[tid], key = 2.f;
            if (uu != 0.f) { float t = -vv / uu; if (t > 0.f && t < 1.f) key = t; }
            s_cuk[tid] = key;
        }
        __syncthreads();
        // rank-by-counting, disjoint warp sets
        if (tid < 256) {
            float key = s_ctk[tid]; int rank = 0;
            #pragma unroll 16
            for (int j = 0; j < 256; j++) {
                float kj = s_ctk[j];
                rank += (kj < key) || (kj == key && j < tid);
            }
            s_st[rank] = key;
            g_pos[tid] = rank + 1;
        } else if (tid < 384) {
            int k = tid - 256;
            float key = s_cuk[k]; int rank = 0;
            #pragma unroll 16
            for (int j = 0; j < 128; j++) {
                float kj = s_cuk[j];
                rank += (kj < key) || (kj == key && j < k);
            }
            s_su[rank] = key; s_cuo[rank] = k;
        }
        if (tid == 0) { s_st[256] = 2.f; s_su[128] = 2.f; }
        for (int b = tid; b < LUTN; b += NTHR) { s_lutU[b] = 0; s_lutV[b] = 0; }
        __syncthreads();
        // LUT scatter fill (LUTN power of 2 -> key*LUTN exact)
        {
            int k = tid >> 2, g = tid & 3;               // k in 0..127
            float k0 = s_su[k], k1 = s_su[k + 1];
            int st_ = min((int)ceilf(k0 * (float)LUTN), LUTN);
            int en  = min((int)ceilf(k1 * (float)LUTN), LUTN);
            for (int b = st_ + g; b < en; b += 4) s_lutU[b] = (unsigned short)(k + 1);
        }
        {
            int k = tid >> 1, g = tid & 1;               // k in 0..255
            float k0 = s_st[k], k1 = s_st[k + 1];
            int st_ = min((int)ceilf(k0 * (float)LUTN), LUTN);
            int en  = min((int)ceilf(k1 * (float)LUTN), LUTN);
            for (int b = st_ + g; b < en; b += 2) s_lutV[b] = (unsigned short)(k + 1);
        }
        // A0/B0 at midpoint of first u-segment
        float em0 = 0.5f * fminf(s_su[0], 1.f);
        {
            float a0 = 0.f, b0 = 0.f;
            if (tid < 128 && fmaf(s_cu[tid], em0, s_cv[tid]) > 0.f) {
                a0 = s_cu[tid] * s_cw2b[tid]; b0 = s_cv[tid] * s_cw2b[tid];
            }
            #pragma unroll
            for (int o = 16; o > 0; o >>= 1) {
                a0 += __shfl_xor_sync(~0u, a0, o);
                b0 += __shfl_xor_sync(~0u, b0, o);
            }
            if (lane == 0) { s_wa[wid] = a0; s_wb[wid] = b0; }
        }
        __syncthreads();
        float A0 = s_wa[0] + s_wa[1] + s_wa[2] + s_wa[3];
        float B0 = s_wb[0] + s_wb[1] + s_wb[2] + s_wb[3] + __ldg(b2b);
        __syncthreads();
        {   // inclusive shuffle scan of flip deltas over sorted u-slots
            float dA = 0.f, dB = 0.f;
            if (tid < 128) {
                float key = s_su[tid];
                if (key < 1.f) {
                    int i = s_cuo[tid];
                    float sg = (s_cu[i] > 0.f) ? 1.f : -1.f;
                    dA = sg * s_cu[i] * s_cw2b[i];
                    dB = sg * s_cv[i] * s_cw2b[i];
                }
            }
            float ia = dA, ib = dB;
            #pragma unroll
            for (int o = 1; o < 32; o <<= 1) {
                float ta = __shfl_up_sync(~0u, ia, o), tb = __shfl_up_sync(~0u, ib, o);
                if (lane >= o) { ia += ta; ib += tb; }
            }
            if (tid < 128 && lane == 31) { s_wa[8 + wid] = ia; s_wb[8 + wid] = ib; }
            __syncthreads();
            if (tid < 128) {
                float oa = 0.f, ob = 0.f;
                for (int w = 0; w < wid; w++) { oa += s_wa[8 + w]; ob += s_wb[8 + w]; }
                s_uA[tid + 1] = A0 + ia + oa;
                s_uB[tid + 1] = B0 + ib + ob;
            }
            if (tid == 0) { s_uA[0] = A0; s_uB[0] = B0; }
        }
        __syncthreads();
        {   // gmax over segment endpoints
            float gm = -3.0e38f;
            if (tid <= 128) {
                float lo = tid ? fminf(s_su[tid - 1], 1.f) : 0.f;
                float hi = (tid < 128) ? fminf(s_su[tid], 1.f) : 1.f;
                gm = fmaxf(fmaf(s_uA[tid], lo, s_uB[tid]), fmaf(s_uA[tid], hi, s_uB[tid]));
            }
            #pragma unroll
            for (int o = 16; o > 0; o >>= 1) gm = fmaxf(gm, __shfl_xor_sync(~0u, gm, o));
            if (lane == 0) s_wa[wid] = gm;
            __syncthreads();
            if (tid == 0) {
                float g = s_wa[0];
                #pragma unroll
                for (int w = 1; w < 16; w++) g = fmaxf(g, s_wa[w]);
                g_gmaxv = g;
            }
        }
        __syncthreads();
        // publish tables (plain stores), then correct ticket idiom
        if (tid < 129) { g_gsu[tid] = s_su[tid]; g_guA[tid] = s_uA[tid]; g_guB[tid] = s_uB[tid]; }
        if (tid < 257) g_gst[tid] = s_st[tid];
        for (int b = tid; b < LUTN; b += NTHR)
            g_glut[b] = ((unsigned)s_lutU[b] << 16) | (unsigned)s_lutV[b];
        sigall(&g_tab);
    }

    // ================= gate: tables ready (one-way; block 0 passes instantly) =================
    waitge(&g_tab, ep + 1u);
    s_lut[tid] = g_glut[tid];                       // plain loads (same-launch data)
    s_lut[tid + 512] = g_glut[tid + 512];
    if (tid < 129) { s_su[tid] = g_gsu[tid]; s_uA[tid] = g_guA[tid]; s_uB[tid] = g_guB[tid]; }
    if (tid < 257) { s_st[tid] = g_gst[tid]; s_bW[tid] = 0.f; s_bWE[tid] = 0.f; }
    __syncthreads();
    float gmax = g_gmaxv;

    // ================= edge pass (registers; leftovers via generic loops) =================
    {
        float es[8] = {e0.x, e0.y, e0.z, e0.w, e1.x, e1.y, e1.z, e1.w};
        #pragma unroll
        for (int j = 0; j < 8; j++) {
            float e = es[j];
            if (e > 0.f && e < 1.f) {               // preload pads (2.0) skipped
                unsigned lv = s_lut[min((int)(e * (float)LUTN), LUTN - 1)];
                int useg = min((int)(lv >> 16), 128), vbin = min((int)(lv & 0xffffu), 256);
                while (useg < 128 && s_su[useg] <= e) useg++;
                while (vbin < 256 && s_st[vbin] <= e) vbin++;
                float w = __expf(fmaf(s_uA[useg], e, s_uB[useg]) - gmax);
                atomicAdd(&s_bW[vbin], w);
                atomicAdd(&s_bWE[vbin], w * e);
            }
        }
        for (int q = q0 + 2 * stride; q < nq; q += stride) {
            float4 v = __ldg(a4 + q);
            float ee[4] = {v.x, v.y, v.z, v.w};
            #pragma unroll
            for (int j = 0; j < 4; j++) {
                float e = ee[j];
                if (e > 0.f && e < 1.f) {
                    unsigned lv = s_lut[min((int)(e * (float)LUTN), LUTN - 1)];
                    int useg = min((int)(lv >> 16), 128), vbin = min((int)(lv & 0xffffu), 256);
                    while (useg < 128 && s_su[useg] <= e) useg++;
                    while (vbin < 256 && s_st[vbin] <= e) vbin++;
                    float w = __expf(fmaf(s_uA[useg], e, s_uB[useg]) - gmax);
                    atomicAdd(&s_bW[vbin], w);
                    atomicAdd(&s_bWE[vbin], w * e);
                }
            }
        }
        for (int pp = (nq << 2) + bid * NTHR + tid; pp < P; pp += stride) {
            float e = __ldg(adj + pp);
            if (e > 0.f && e < 1.f) {
                unsigned lv = s_lut[min((int)(e * (float)LUTN), LUTN - 1)];
                int useg = min((int)(lv >> 16), 128), vbin = min((int)(lv & 0xffffu), 256);
                while (useg < 128 && s_su[useg] <= e) useg++;
                while (vbin < 256 && s_st[vbin] <= e) vbin++;
                float w = __expf(fmaf(s_uA[useg], e, s_uB[useg]) - gmax);
                atomicAdd(&s_bW[vbin], w);
                atomicAdd(&s_bWE[vbin], w * e);
            }
        }
    }
    __syncthreads();
    if (tid < 257) {
        float w = s_bW[tid], we = s_bWE[tid];
        if (w != 0.f || we != 0.f) {
            atomicAdd(&d_binW[tid], w);
            atomicAdd(&d_binWE[tid], we);
        }
    }
    sigall(&g_flush);
    if (bid >= 4) return;                            // producers never wait past here

    // ================= tail: 4 waiter blocks =================
    waitge(&g_flush, (ep + 1u) * (unsigned)NGRID);

    // scan over 257 bins (redundant per waiter; plain loads)
    {
        float binw = 0.f, binwe = 0.f;
        if (tid < 257) { binw = d_binW[tid]; binwe = d_binWE[tid]; }
        float ia = binw, ib = binwe;
        #pragma unroll
        for (int o = 1; o < 32; o <<= 1) {
            float ta = __shfl_up_sync(~0u, ia, o), tb = __shfl_up_sync(~0u, ib, o);
            if (lane >= o) { ia += ta; ib += tb; }
        }
        if (lane == 31 && wid < 9) { s_wa[wid] = ia; s_wb[wid] = ib; }
        __syncthreads();
        if (tid < 257) {
            float oa = 0.f, ob = 0.f;
            for (int w = 0; w < wid; w++) { oa += s_wa[w]; ob += s_wb[w]; }
            s_PF[tid] = ia + oa; s_PG[tid] = ib + ob;
        }
    }
    __syncthreads();
    float Z = s_PF[256], Gtot = s_PG[256];
    float invZ = (Z > 0.f) ? (1.f / Z) : 0.f;
    float S0   = (Z > 0.f) ? 1.f : 0.f;

    // Hn per dim (plain loads of same-launch tables)
    if (tid < 256) {
        float r = g_rr[tid], s = g_ss[tid];
        int m = g_pos[tid];
        float H;
        if (r > 0.f)      H = r * (Gtot - s_PG[m - 1]) + s * (Z - s_PF[m - 1]);
        else if (r < 0.f) H = r * s_PG[m - 1] + s * s_PF[m - 1];
        else              H = (s > 0.f) ? s * Z : 0.f;
        s_Hn[tid] = H * invZ;
    }
    __syncthreads();

    // full Wt per waiter (4 teams x 64 d-rows of W3b)
    {
        float a2 = 0.f; int d0 = team * 64;
        #pragma unroll 8
        for (int d = d0; d < d0 + 64; d++)
            a2 = fmaf(s_Hn[d], __ldg(W3b + d * 128 + col), a2);
        s_pa[team][col] = a2;
    }
    __syncthreads();
    if (tid < 128)
        s_Wt[tid] = s_pa[0][tid] + s_pa[1][tid] + s_pa[2][tid] + s_pa[3][tid] + S0 * __ldg(b3b + tid);
    __syncthreads();

    // h4 slice: n in [bid*64, bid*64+64)
    {
        int o = tid & 63, g8 = tid >> 6;             // 8 groups x 16 m-rows
        float p = 0.f; int m0 = g8 * 16;
        #pragma unroll
        for (int m = m0; m < m0 + 16; m++)
            p = fmaf(s_Wt[m], __ldg(W4a + m * 256 + bid * 64 + o), p);
        s_red[g8 * 64 + o] = p;
    }
    __syncthreads();
    if (tid < 64) {
        float h = __ldg(b4a + bid * 64 + tid);
        #pragma unroll
        for (int g8 = 0; g8 < 8; g8++) h += s_red[g8 * 64 + tid];
        s_h4[tid] = fmaxf(h, 0.f);
    }
    __syncthreads();

    // out partials over this waiter's 64 n-rows of W4b -> atomic accumulator
    {
        int o = tid & 63, g8 = tid >> 6;             // 8 groups x 8 n-rows
        float p = 0.f;
        #pragma unroll
        for (int q = 0; q < 8; q++) {
            int nl = g8 * 8 + q;
            p = fmaf(s_h4[nl], __ldg(W4b + (bid * 64 + nl) * 64 + o), p);
        }
        s_red[g8 * 64 + o] = p;
    }
    __syncthreads();
    if (tid < 64) {
        float p = 0.f;
        #pragma unroll
        for (int g8 = 0; g8 < 8; g8++) p += s_red[g8 * 64 + tid];
        atomicAdd(&g_outAcc[tid], p);
    }
    sigall(&g_tail);
    if (bid != 0) return;

    // ================= block 0: finalize + reset state for next replay =================
    waitge(&g_tail, (ep + 1u) * 4u);
    if (tid < 64) {
        float o = __ldg(b4b + tid) + g_outAcc[tid];  // plain load of atomic-written data
        out[tid] = o;
        g_outAcc[tid] = 0.f;
    }
    if (tid < 257) { d_binW[tid] = 0.f; d_binWE[tid] = 0.f; }
}

// ---------------- launch: ONE kernel, one graph node ----------------
extern "C" void kernel_launch(void* const* d_in, const int* in_sizes, int n_in,
                              void* d_out, int out_size) {
    const float* adj = (const float*)d_in[1];
    int P = in_sizes[1];
    kAll<<<NGRID, NTHR>>>(adj, P,
        (const float*)d_in[3],  (const float*)d_in[4],
        (const float*)d_in[5],  (const float*)d_in[6],
        (const float*)d_in[7],  (const float*)d_in[8],
        (const float*)d_in[9],  (const float*)d_in[10],
        (const float*)d_in[11], (const float*)d_in[12],
        (const float*)d_in[13], (const float*)d_in[14],
        (const float*)d_in[15], (const float*)d_in[16],
        (const float*)d_in[17], (const float*)d_in[18],
        (float*)d_out);
}